// round 15
// baseline (speedup 1.0000x reference)
#include <cuda_runtime.h>
#include <cstdint>

// 2D Haar DWT, fp32, input (8, 64, 512, 512) -> 4x (8, 64, 256, 256)
// Output d_out = [ll | lh | hl | hh], each 8*64*256*256 floats.
//
// R15: R13 structure (LDG.128 + warp-distributed TMA bulk stores + early
// exit, 512-thr / 16-warp barrier) with 2 items per thread: 1024 items per
// block, MLP=4 front-batched loads, 8 KB bulk per subband, 16384 blocks.
// Isolates R8's regression cause (32-warp barrier vs block granularity).

#define PLANES      512          // 8 * 64
#define IN_W        512
#define OUT_W       256
#define OUT_H       256
#define PLANE_IN_F4   (IN_W * 512 / 4)     // 65536 float4 per input plane
#define ROW_IN_F4     (IN_W / 4)           // 128 float4 per input row
#define ROW_OUT_F2    (OUT_W / 2)          // 128 float2 per output row
#define SUBBAND_ELEMS (PLANES * OUT_W * OUT_H)  // 33554432 floats per subband

#define BLOCK_THR   512
#define ITEMS_BLK   (BLOCK_THR * 2)        // 1024 items per block
#define SUB_BYTES   (ITEMS_BLK * 8)        // 8192 bytes per subband per block

__global__ __launch_bounds__(BLOCK_THR)
void dwt2d_haar_kernel(const float4* __restrict__ x4,
                       float* __restrict__ out)
{
    __shared__ alignas(128) float2 s[4][ITEMS_BLK];   // 32 KB staged output

    unsigned tid   = threadIdx.x;
    unsigned item0 = blockIdx.x * ITEMS_BLK + tid;            // first item
    unsigned item1 = item0 + BLOCK_THR;                       // second item

    const float half = 0.5f;

    // ---- Phase 1: two patches per thread, front-batched loads (MLP=4) ----
    unsigned ox2_0 = item0 & (ROW_OUT_F2 - 1);
    unsigned t1_0  = item0 >> 7;
    unsigned oy_0  = t1_0 & (OUT_H - 1);
    unsigned p_0   = t1_0 >> 8;
    unsigned ib_0  = p_0 * PLANE_IN_F4 + (2u * oy_0) * ROW_IN_F4 + ox2_0;

    unsigned ox2_1 = item1 & (ROW_OUT_F2 - 1);
    unsigned t1_1  = item1 >> 7;
    unsigned oy_1  = t1_1 & (OUT_H - 1);
    unsigned p_1   = t1_1 >> 8;
    unsigned ib_1  = p_1 * PLANE_IN_F4 + (2u * oy_1) * ROW_IN_F4 + ox2_1;

    float4 q0 = __ldcg(&x4[ib_0]);
    float4 q1 = __ldcg(&x4[ib_0 + ROW_IN_F4]);
    float4 q2 = __ldcg(&x4[ib_1]);
    float4 q3 = __ldcg(&x4[ib_1 + ROW_IN_F4]);

    {
        float a0 = q0.x, b0 = q0.y, c0 = q1.x, d0 = q1.y;
        float a1 = q0.z, b1 = q0.w, c1 = q1.z, d1 = q1.w;
        float2 vll, vlh, vhl, vhh;
        vll.x = (a0 + b0 + c0 + d0) * half;
        vll.y = (a1 + b1 + c1 + d1) * half;
        vlh.x = (c0 + d0 - a0 - b0) * half;
        vlh.y = (c1 + d1 - a1 - b1) * half;
        vhl.x = (b0 + d0 - a0 - c0) * half;
        vhl.y = (b1 + d1 - a1 - c1) * half;
        vhh.x = (a0 + d0 - b0 - c0) * half;
        vhh.y = (a1 + d1 - b1 - c1) * half;
        s[0][tid] = vll;
        s[1][tid] = vlh;
        s[2][tid] = vhl;
        s[3][tid] = vhh;
    }
    {
        float a0 = q2.x, b0 = q2.y, c0 = q3.x, d0 = q3.y;
        float a1 = q2.z, b1 = q2.w, c1 = q3.z, d1 = q3.w;
        float2 vll, vlh, vhl, vhh;
        vll.x = (a0 + b0 + c0 + d0) * half;
        vll.y = (a1 + b1 + c1 + d1) * half;
        vlh.x = (c0 + d0 - a0 - b0) * half;
        vlh.y = (c1 + d1 - a1 - b1) * half;
        vhl.x = (b0 + d0 - a0 - c0) * half;
        vhl.y = (b1 + d1 - a1 - c1) * half;
        vhh.x = (a0 + d0 - b0 - c0) * half;
        vhh.y = (a1 + d1 - b1 - c1) * half;
        s[0][tid + BLOCK_THR] = vll;
        s[1][tid + BLOCK_THR] = vlh;
        s[2][tid + BLOCK_THR] = vhl;
        s[3][tid + BLOCK_THR] = vhh;
    }

    __syncthreads();

    // ---- Phase 2: 4x TMA bulk store (8 KB each), one per warp 0..3. ----
    unsigned wid = tid >> 5;
    if (wid < 4) {
        uint32_t epred;
        asm volatile(
            "{\n\t"
            ".reg .pred p;\n\t"
            "elect.sync _|p, 0xFFFFFFFF;\n\t"
            "selp.b32 %0, 1, 0, p;\n\t"
            "}" : "=r"(epred));
        if (epred) {
            asm volatile("fence.proxy.async.shared::cta;" ::: "memory");
            unsigned sub = wid;
            // block owns float2 range [blockIdx.x*1024, +1024) per subband
            size_t base_f = (size_t)blockIdx.x * (2u * ITEMS_BLK);
            float* gptr = out + (size_t)sub * SUBBAND_ELEMS + base_f;
            uint32_t saddr;
            asm("{ .reg .u64 t; cvta.to.shared.u64 t, %1; cvt.u32.u64 %0, t; }"
                : "=r"(saddr) : "l"(&s[sub][0]));
            asm volatile(
                "cp.async.bulk.global.shared::cta.bulk_group [%0], [%1], %2;"
                :: "l"(gptr), "r"(saddr), "r"((uint32_t)SUB_BYTES)
                : "memory");
            asm volatile("cp.async.bulk.commit_group;" ::: "memory");
            // Wait until smem read-out done; global writes drain async.
            asm volatile("cp.async.bulk.wait_group.read 0;" ::: "memory");
        }
    }
    // Non-issuing threads exit; CTA (and smem) persists until the four
    // issuing threads complete their wait_group.
}

extern "C" void kernel_launch(void* const* d_in, const int* in_sizes, int n_in,
                              void* d_out, int out_size)
{
    const float4* x4 = (const float4*)d_in[0];
    float* out = (float*)d_out;

    const unsigned total_items = PLANES * OUT_H * ROW_OUT_F2;   // 16,777,216
    const unsigned grid = total_items / ITEMS_BLK;              // 16,384

    dwt2d_haar_kernel<<<grid, BLOCK_THR>>>(x4, out);
}

// round 16
// speedup vs baseline: 1.0031x; 1.0031x over previous
#include <cuda_runtime.h>
#include <cstdint>

// 2D Haar DWT, fp32, input (8, 64, 512, 512) -> 4x (8, 64, 256, 256)
// Output d_out = [ll | lh | hl | hh], each 8*64*256*256 floats.
//
// FINAL (R13 confirmation): phase-separated streaming.
//   Phase 1: per-thread 2x LDG.128 (L1-bypass) -> compute -> stage to smem.
//   Phase 2: 4x TMA bulk stores (4 KB per subband), one per warp (elected
//            lane, own bulk group), non-issuing warps exit early.
// Design matrix fully explored (R1-R15); this config measured best:
// ncu 148.2us, DRAM 87.0%, 6.90 TB/s. Residual idle = HBM R/W turnaround.

#define PLANES      512          // 8 * 64
#define IN_W        512
#define OUT_W       256
#define OUT_H       256
#define PLANE_IN_F4   (IN_W * 512 / 4)     // 65536 float4 per input plane
#define ROW_IN_F4     (IN_W / 4)           // 128 float4 per input row
#define ROW_OUT_F2    (OUT_W / 2)          // 128 float2 per output row
#define SUBBAND_ELEMS (PLANES * OUT_W * OUT_H)  // 33554432 floats per subband

#define BLOCK_THR   512
#define SUB_BYTES   (BLOCK_THR * 8)        // 4096 bytes per subband per block

__global__ __launch_bounds__(BLOCK_THR)
void dwt2d_haar_kernel(const float4* __restrict__ x4,
                       float* __restrict__ out)
{
    __shared__ alignas(128) float2 s[4][BLOCK_THR];   // 16 KB staged output

    unsigned tid  = threadIdx.x;
    unsigned item = blockIdx.x * BLOCK_THR + tid;
    // item == output float2 index within each subband (exact identity).

    // ---- Phase 1: 2x LDG.128 (L1-bypass), compute, stage to smem ----
    unsigned ox2 = item & (ROW_OUT_F2 - 1);         // 0..127
    unsigned t1  = item >> 7;
    unsigned oy  = t1 & (OUT_H - 1);                // 0..255
    unsigned p   = t1 >> 8;                         // 0..511

    unsigned in_base = p * PLANE_IN_F4 + (2u * oy) * ROW_IN_F4 + ox2;
    float4 r0 = __ldcg(&x4[in_base]);               // row 2y,   cols 4x..4x+3
    float4 r1 = __ldcg(&x4[in_base + ROW_IN_F4]);   // row 2y+1

    float a0 = r0.x, b0 = r0.y, c0 = r1.x, d0 = r1.y;
    float a1 = r0.z, b1 = r0.w, c1 = r1.z, d1 = r1.w;

    const float half = 0.5f;
    float2 vll, vlh, vhl, vhh;
    vll.x = (a0 + b0 + c0 + d0) * half;
    vll.y = (a1 + b1 + c1 + d1) * half;
    vlh.x = (c0 + d0 - a0 - b0) * half;
    vlh.y = (c1 + d1 - a1 - b1) * half;
    vhl.x = (b0 + d0 - a0 - c0) * half;
    vhl.y = (b1 + d1 - a1 - c1) * half;
    vhh.x = (a0 + d0 - b0 - c0) * half;
    vhh.y = (a1 + d1 - b1 - c1) * half;

    s[0][tid] = vll;
    s[1][tid] = vlh;
    s[2][tid] = vhl;
    s[3][tid] = vhh;

    __syncthreads();

    // ---- Phase 2: 4x TMA bulk store (4 KB each), one per warp 0..3. ----
    unsigned wid = tid >> 5;
    if (wid < 4) {
        uint32_t epred;
        asm volatile(
            "{\n\t"
            ".reg .pred p;\n\t"
            "elect.sync _|p, 0xFFFFFFFF;\n\t"
            "selp.b32 %0, 1, 0, p;\n\t"
            "}" : "=r"(epred));
        if (epred) {
            asm volatile("fence.proxy.async.shared::cta;" ::: "memory");
            unsigned sub = wid;
            // block owns float2 range [blockIdx.x*512, +512) in each subband
            size_t base_f = (size_t)blockIdx.x * (2u * BLOCK_THR);
            float* gptr = out + (size_t)sub * SUBBAND_ELEMS + base_f;
            uint32_t saddr;
            asm("{ .reg .u64 t; cvta.to.shared.u64 t, %1; cvt.u32.u64 %0, t; }"
                : "=r"(saddr) : "l"(&s[sub][0]));
            asm volatile(
                "cp.async.bulk.global.shared::cta.bulk_group [%0], [%1], %2;"
                :: "l"(gptr), "r"(saddr), "r"((uint32_t)SUB_BYTES)
                : "memory");
            asm volatile("cp.async.bulk.commit_group;" ::: "memory");
            // Wait until smem read-out done; global writes drain async.
            asm volatile("cp.async.bulk.wait_group.read 0;" ::: "memory");
        }
    }
    // Non-issuing threads exit; CTA (and smem) persists until the four
    // issuing threads complete their wait_group.
}

extern "C" void kernel_launch(void* const* d_in, const int* in_sizes, int n_in,
                              void* d_out, int out_size)
{
    const float4* x4 = (const float4*)d_in[0];
    float* out = (float*)d_out;

    const unsigned total_threads = PLANES * OUT_H * ROW_OUT_F2;  // 16,777,216
    const unsigned grid = total_threads / BLOCK_THR;             // 32,768

    dwt2d_haar_kernel<<<grid, BLOCK_THR>>>(x4, out);
}